// round 15
// baseline (speedup 1.0000x reference)
#include <cuda_runtime.h>
#include <cuda_fp16.h>
#include <math.h>
#include <stdint.h>

#define B_SZ   2
#define LSEQ   1024
#define DM     1024
#define DI     2048
#define DS     16
#define MROWS  (B_SZ * LSEQ)   // 2048
#define NCHUNK 16
#define CLEN   (LSEQ / NCHUNK) // 64
#define NDBC   2176            // 2048 delta + 32 B/C + 96 pad (17 * 128)

// ---------------------------------------------------------------------------
// Scratch (__device__ globals; zero-initialized -> padding rows stay 0)
// ---------------------------------------------------------------------------
__device__ __half g_xzh[MROWS * 2 * DI];
__device__ __half g_xconvh[MROWS * DI];
__device__ __half g_dbch[MROWS * NDBC];
__device__ float  g_mmout[MROWS * DM];
__device__ __half g_xh[MROWS * DM];
__device__ __half g_yzh[MROWS * DI];
__device__ __half g_wt_in[(2 * DI) * DM];
__device__ __half g_wt_dtx[NDBC * DI];
__device__ __half g_wt_out[DM * DI];
__device__ float  g_E[B_SZ * DI * NCHUNK * DS];
__device__ float  g_S[B_SZ * DI * NCHUNK];
__device__ float  g_Hi[B_SZ * DI * NCHUNK * DS];

// ---------------------------------------------------------------------------
// helpers
// ---------------------------------------------------------------------------
static __device__ __forceinline__ uint32_t smem_u32(const void* p) {
    uint32_t a;
    asm("{ .reg .u64 t; cvta.to.shared.u64 t, %1; cvt.u32.u64 %0, t; }"
        : "=r"(a) : "l"(p));
    return a;
}
static __device__ __forceinline__ void cp_async16(uint32_t sa, const void* ga) {
    asm volatile("cp.async.cg.shared.global [%0], [%1], 16;" :: "r"(sa), "l"(ga));
}
static __device__ __forceinline__ void cp_commit() {
    asm volatile("cp.async.commit_group;" ::: "memory");
}
static __device__ __forceinline__ void cp_wait2() {
    asm volatile("cp.async.wait_group 2;" ::: "memory");
}
static __device__ __forceinline__ float ex2f(float x) {
    float r;
    asm("ex2.approx.f32 %0, %1;" : "=f"(r) : "f"(x));
    return r;
}
static __device__ __forceinline__ void mma16816(float* d, const uint32_t* a,
                                                const uint32_t* b) {
    asm volatile(
        "mma.sync.aligned.m16n8k16.row.col.f32.f16.f16.f32 "
        "{%0,%1,%2,%3}, {%4,%5,%6,%7}, {%8,%9}, {%0,%1,%2,%3};"
        : "+f"(d[0]), "+f"(d[1]), "+f"(d[2]), "+f"(d[3])
        : "r"(a[0]), "r"(a[1]), "r"(a[2]), "r"(a[3]), "r"(b[0]), "r"(b[1]));
}
static __device__ __forceinline__ void ldsm_x4(uint32_t* r, uint32_t addr) {
    asm volatile("ldmatrix.sync.aligned.m8n8.x4.shared.b16 {%0,%1,%2,%3}, [%4];"
                 : "=r"(r[0]), "=r"(r[1]), "=r"(r[2]), "=r"(r[3]) : "r"(addr));
}
static __device__ __forceinline__ void ldsm_x2(uint32_t* r, uint32_t addr) {
    asm volatile("ldmatrix.sync.aligned.m8n8.x2.shared.b16 {%0,%1}, [%2];"
                 : "=r"(r[0]), "=r"(r[1]) : "r"(addr));
}

// ---------------------------------------------------------------------------
// fp16 mma.sync GEMM (fp32 accum), templated tiles (R13-proven mainloop).
// __launch_bounds__(NTHR, 2) is load-bearing: caps regs at 128 -> occ 2.
// EPI: 0 bias; 1 bias+softplus; 2 combined delta/BC; 3 bias + residual(bias2).
// OUTH: 1 -> store __half, 0 -> store float.
// ---------------------------------------------------------------------------
#define BK 32
#define STRDH 40
#define NSTG 4

template <int TBM, int TBN, int TWM, int TWN, int NTHR, int EPI, int OUTH>
__global__ __launch_bounds__(NTHR, 2)
void gemm_mma(const __half* __restrict__ A, const __half* __restrict__ Bt,
              const float* __restrict__ bias, const float* __restrict__ bias2,
              void* __restrict__ Cv, int M, int N, int K)
{
    constexpr int ATILE = TBM * STRDH;
    constexpr int BTILE = TBN * STRDH;
    constexpr int NWN = TBN / TWN;
    constexpr int MI = TWM / 16;
    constexpr int NI = TWN / 8;

    extern __shared__ __half smh[];
    __half* As = smh;
    __half* Bs = smh + NSTG * ATILE;

    const int tid  = threadIdx.x;
    const int lane = tid & 31;
    const int wid  = tid >> 5;
    const int wm   = (wid / NWN) * TWM;
    const int wn   = (wid % NWN) * TWN;
    const int bm = blockIdx.y * TBM;
    const int bn = blockIdx.x * TBN;

    float acc[MI][NI][4];
#pragma unroll
    for (int mi = 0; mi < MI; mi++)
#pragma unroll
        for (int ni = 0; ni < NI; ni++)
#pragma unroll
            for (int r = 0; r < 4; r++) acc[mi][ni][r] = 0.f;

    auto load_tile = [&](int j) {
        const int stg = j % NSTG;
        const int k0 = j * BK;
        __half* ad = As + stg * ATILE;
        __half* bd = Bs + stg * BTILE;
#pragma unroll
        for (int ch = tid; ch < TBM * 4; ch += NTHR) {
            int row = ch >> 2, col = ch & 3;
            cp_async16(smem_u32(ad + row * STRDH + col * 8),
                       A + (size_t)(bm + row) * K + k0 + col * 8);
        }
#pragma unroll
        for (int ch = tid; ch < TBN * 4; ch += NTHR) {
            int row = ch >> 2, col = ch & 3;
            cp_async16(smem_u32(bd + row * STRDH + col * 8),
                       Bt + (size_t)(bn + row) * K + k0 + col * 8);
        }
    };

    const int KT = K / BK;
    load_tile(0); cp_commit();
    load_tile(1); cp_commit();
    load_tile(2); cp_commit();

    for (int i = 0; i < KT; i++) {
        cp_wait2();
        __syncthreads();
        if (i + 3 < KT) load_tile(i + 3);
        cp_commit();

        const int stg = i % NSTG;
        const __half* ad = As + stg * ATILE;
        const __half* bd = Bs + stg * BTILE;

#pragma unroll
        for (int kk = 0; kk < BK; kk += 16) {
            uint32_t af[MI][4];
            uint32_t bf[NI][2];
#pragma unroll
            for (int mi = 0; mi < MI; mi++) {
                uint32_t a_addr = smem_u32(
                    ad + (wm + mi * 16 + (lane & 15)) * STRDH + kk + (lane >> 4) * 8);
                ldsm_x4(af[mi], a_addr);
            }
#pragma unroll
            for (int ni = 0; ni < NI; ni++) {
                uint32_t b_addr = smem_u32(
                    bd + (wn + ni * 8 + (lane & 7)) * STRDH + kk + ((lane >> 3) & 1) * 8);
                ldsm_x2(bf[ni], b_addr);
            }
#pragma unroll
            for (int mi = 0; mi < MI; mi++)
#pragma unroll
                for (int ni = 0; ni < NI; ni++)
                    mma16816(acc[mi][ni], af[mi], bf[ni]);
        }
    }

    // ---- epilogue ---------------------------------------------------------
#pragma unroll
    for (int mi = 0; mi < MI; mi++) {
#pragma unroll
        for (int ni = 0; ni < NI; ni++) {
            int r0 = bm + wm + mi * 16 + (lane >> 2);
            int c0 = bn + wn + ni * 8 + (lane & 3) * 2;
            float2 bv;
            bool sp;
            if (EPI == 2) {
                if (c0 < DI)            { bv = *(const float2*)(bias + c0);       sp = true;  }
                else if (c0 < DI + 32)  { bv = *(const float2*)(bias2 + c0 - DI); sp = false; }
                else                    { bv = make_float2(0.f, 0.f);             sp = false; }
            } else {
                bv = *(const float2*)(bias + c0);
                sp = (EPI == 1);
            }
            float2 v0, v1;
            v0.x = acc[mi][ni][0] + bv.x;
            v0.y = acc[mi][ni][1] + bv.y;
            v1.x = acc[mi][ni][2] + bv.x;
            v1.y = acc[mi][ni][3] + bv.y;
            if (EPI == 3) {        // residual add from bias2 (row-major [M,N] fp32)
                const float* xr = bias2;
                float2 a0 = *(const float2*)(xr + (size_t)r0 * N + c0);
                float2 a1 = *(const float2*)(xr + (size_t)(r0 + 8) * N + c0);
                v0.x += a0.x; v0.y += a0.y;
                v1.x += a1.x; v1.y += a1.y;
            }
            if (sp) {
                v0.x = (v0.x > 15.f) ? v0.x : log1pf(__expf(v0.x));
                v0.y = (v0.y > 15.f) ? v0.y : log1pf(__expf(v0.y));
                v1.x = (v1.x > 15.f) ? v1.x : log1pf(__expf(v1.x));
                v1.y = (v1.y > 15.f) ? v1.y : log1pf(__expf(v1.y));
            }
            if (OUTH) {
                __half* C = (__half*)Cv;
                *(__half2*)(C + (size_t)r0 * N + c0) = __floats2half2_rn(v0.x, v0.y);
                *(__half2*)(C + (size_t)(r0 + 8) * N + c0) = __floats2half2_rn(v1.x, v1.y);
            } else {
                float* C = (float*)Cv;
                *(float2*)(C + (size_t)r0 * N + c0) = v0;
                *(float2*)(C + (size_t)(r0 + 8) * N + c0) = v1;
            }
        }
    }
}

#define GSMEM_128 ((128 + 128) * STRDH * 2 * NSTG)   // 81920
#define GSMEM_G3  ((64 + 128) * STRDH * 2 * NSTG)    // 61440

// ---------------------------------------------------------------------------
// Fused prep: to_half(x) + 4 weight transposes, one launch.
// Block ranges: [0,2048) to_half | [2048,6144) W_in | [6144,10240) W_dt |
//               [10240,10304) W_xp | [10304,12352) W_out
// ---------------------------------------------------------------------------
static __device__ __forceinline__ void tw_tile(const float* __restrict__ W,
                                               __half* __restrict__ Wt,
                                               int K, int N, int bx, int by,
                                               float (*t)[33])
{
    int n0 = bx * 32, k0 = by * 32;
    int tx = threadIdx.x & 31, ty = threadIdx.x >> 5;
#pragma unroll
    for (int i = ty; i < 32; i += 8)
        t[i][tx] = W[(size_t)(k0 + i) * N + n0 + tx];
    __syncthreads();
#pragma unroll
    for (int i = ty; i < 32; i += 8)
        Wt[(size_t)(n0 + i) * K + k0 + tx] = __float2half(t[tx][i]);
}

__global__ __launch_bounds__(256)
void prep_all(const float* __restrict__ x, const float* __restrict__ W_in,
              const float* __restrict__ W_dt, const float* __restrict__ W_xp,
              const float* __restrict__ W_out)
{
    __shared__ float t[32][33];
    int b = blockIdx.x;
    if (b < 2048) {                       // to_half, float4 x 4/thread
        int i = (b * 256 + threadIdx.x) * 4;
        float4 v = *(const float4*)(x + i);
        __half2 h0 = __floats2half2_rn(v.x, v.y);
        __half2 h1 = __floats2half2_rn(v.z, v.w);
        *(__half2*)(g_xh + i) = h0;
        *(__half2*)(g_xh + i + 2) = h1;
        return;
    }
    b -= 2048;
    if (b < 4096) { tw_tile(W_in, g_wt_in, DM, 2 * DI, b & 127, b >> 7, t); return; }
    b -= 4096;
    if (b < 4096) { tw_tile(W_dt, g_wt_dtx, DI, DI, b & 63, b >> 6, t); return; }
    b -= 4096;
    if (b < 64)  { tw_tile(W_xp, g_wt_dtx + (size_t)DI * DI, DI, 32, 0, b, t); return; }
    b -= 64;
    tw_tile(W_out, g_wt_out, DI, DM, b & 31, b >> 5, t);
}

// ---------------------------------------------------------------------------
// Depthwise causal conv (width 4) + SiLU; half2 vectorized (2 channels/thread)
// ---------------------------------------------------------------------------
__global__ __launch_bounds__(256)
void conv_silu(const float* __restrict__ cw, const float* __restrict__ cb)
{
    int e = blockIdx.x * 256 + threadIdx.x;           // over MROWS*DI/2
    if (e >= MROWS * DI / 2) return;
    int d2 = e & (DI / 2 - 1);
    int d  = d2 * 2;
    int lm = e >> 10;                                 // / (DI/2)
    int l  = lm & (LSEQ - 1);

    const __half* xp = g_xzh + (size_t)lm * (2 * DI) + d;
    float ax = cb[d], ay = cb[d + 1];
#pragma unroll
    for (int j = 0; j < 4; j++) {
        int ll = l - 3 + j;
        if (ll >= 0) {
            __half2 xv = *(const __half2*)(xp + (j - 3) * (2 * DI));
            ax += __low2float(xv)  * cw[d * 4 + j];
            ay += __high2float(xv) * cw[(d + 1) * 4 + j];
        }
    }
    ax = ax / (1.f + __expf(-ax));
    ay = ay / (1.f + __expf(-ay));
    *(__half2*)(g_xconvh + (size_t)lm * DI + d) = __floats2half2_rn(ax, ay);
}

// ---------------------------------------------------------------------------
// Chunked scan, d-parallel; half inputs, fp32 state
// ---------------------------------------------------------------------------
#define LOG2E 1.44269504088896f

__global__ __launch_bounds__(128)
void scan_pass1(const float* __restrict__ A_log)
{
    int chunk = blockIdx.x & (NCHUNK - 1);
    int bdg   = blockIdx.x >> 4;
    int bd    = bdg * 128 + threadIdx.x;
    int b     = bd >> 11;
    int d     = bd & (DI - 1);

    __shared__ float bcs[CLEN][DS];
    const __half* bcp = g_dbch + ((size_t)b * LSEQ + chunk * CLEN) * NDBC + DI;
    for (int i = threadIdx.x; i < CLEN * DS; i += 128) {
        int t = i >> 4, s = i & 15;
        bcs[t][s] = __half2float(bcp[(size_t)t * NDBC + s]);
    }
    __syncthreads();

    float Av[DS];
#pragma unroll
    for (int s = 0; s < DS; s++)
        Av[s] = -__expf(A_log[d * DS + s]) * LOG2E;

    float h[DS];
#pragma unroll
    for (int s = 0; s < DS; s++) h[s] = 0.f;
    float S = 0.f;

    const __half* dp = g_dbch + ((size_t)b * LSEQ + chunk * CLEN) * NDBC + d;
    const __half* xp = g_xconvh + ((size_t)b * LSEQ + chunk * CLEN) * DI + d;

    for (int t = 0; t < CLEN; t++) {
        float dv = __half2float(dp[(size_t)t * NDBC]);
        float xv = __half2float(xp[(size_t)t * DI]);
        float u = dv * xv;
        S += dv;
#pragma unroll
        for (int s = 0; s < DS; s++)
            h[s] = fmaf(ex2f(dv * Av[s]), h[s], u * bcs[t][s]);
    }

    int gid = bd * NCHUNK + chunk;
#pragma unroll
    for (int s = 0; s < DS; s++) g_E[gid * DS + s] = h[s];
    g_S[gid] = S;
}

__global__ __launch_bounds__(256)
void scan_combine(const float* __restrict__ A_log)
{
    int idx = blockIdx.x * 256 + threadIdx.x;
    int s  = idx & 15;
    int bd = idx >> 4;
    int d  = bd & (DI - 1);
    float Av = -__expf(A_log[d * DS + s]);
    float H = 0.f;
#pragma unroll
    for (int c = 0; c < NCHUNK; c++) {
        int gid = bd * NCHUNK + c;
        g_Hi[gid * DS + s] = H;
        H = fmaf(__expf(Av * g_S[gid]), H, g_E[gid * DS + s]);
    }
}

__global__ __launch_bounds__(128)
void scan_pass2(const float* __restrict__ A_log, const float* __restrict__ D_skip)
{
    int chunk = blockIdx.x & (NCHUNK - 1);
    int bdg   = blockIdx.x >> 4;
    int bd    = bdg * 128 + threadIdx.x;
    int b     = bd >> 11;
    int d     = bd & (DI - 1);

    __shared__ float bcs[CLEN][2 * DS];
    const __half* bcp = g_dbch + ((size_t)b * LSEQ + chunk * CLEN) * NDBC + DI;
    for (int i = threadIdx.x; i < CLEN * 2 * DS; i += 128) {
        int t = i >> 5, j = i & 31;
        bcs[t][j] = __half2float(bcp[(size_t)t * NDBC + j]);
    }
    __syncthreads();

    float Av[DS];
#pragma unroll
    for (int s = 0; s < DS; s++)
        Av[s] = -__expf(A_log[d * DS + s]) * LOG2E;
    float Dv = D_skip[d];

    int gid = bd * NCHUNK + chunk;
    float h[DS];
#pragma unroll
    for (int s = 0; s < DS; s++) h[s] = g_Hi[gid * DS + s];

    const __half* dp = g_dbch + ((size_t)b * LSEQ + chunk * CLEN) * NDBC + d;
    const __half* xp = g_xconvh + ((size_t)b * LSEQ + chunk * CLEN) * DI + d;
    const __half* zp = g_xzh + ((size_t)b * LSEQ + chunk * CLEN) * (2 * DI) + DI + d;
    __half* yp = g_yzh + ((size_t)b * LSEQ + chunk * CLEN) * DI + d;

    for (int t = 0; t < CLEN; t++) {
        float dv = __half2float(dp[(size_t)t * NDBC]);
        float xv = __half2float(xp[(size_t)t * DI]);
        float z  = __half2float(zp[(size_t)t * (2 * DI)]);
        float u = dv * xv;
        float y = Dv * xv;
#pragma unroll
        for (int s = 0; s < DS; s++) {
            h[s] = fmaf(ex2f(dv * Av[s]), h[s], u * bcs[t][s]);
            y = fmaf(h[s], bcs[t][DS + s], y);
        }
        yp[(size_t)t * DI] = __float2half(y * (z / (1.f + __expf(-z))));
    }
}

// ---------------------------------------------------------------------------
// LayerNorm (residual already folded into g_mmout by gemm3 epilogue)
// ---------------------------------------------------------------------------
__global__ __launch_bounds__(256)
void layernorm(const float* __restrict__ alpha, const float* __restrict__ beta,
               float* __restrict__ out)
{
    __shared__ float red[8];
    int row = blockIdx.x;
    int tid = threadIdx.x;

    float loc[4];
    float sgm = 0.f;
#pragma unroll
    for (int j = 0; j < 4; j++) {
        int i = tid + j * 256;
        loc[j] = g_mmout[(size_t)row * DM + i];
        sgm += loc[j];
    }
#pragma unroll
    for (int o = 16; o; o >>= 1) sgm += __shfl_xor_sync(0xffffffffu, sgm, o);
    if ((tid & 31) == 0) red[tid >> 5] = sgm;
    __syncthreads();
    float tot = red[0];
#pragma unroll
    for (int i = 1; i < 8; i++) tot += red[i];
    float mean = tot * (1.f / DM);
    __syncthreads();

    float q = 0.f;
#pragma unroll
    for (int j = 0; j < 4; j++) {
        float df = loc[j] - mean;
        q += df * df;
    }
#pragma unroll
    for (int o = 16; o; o >>= 1) q += __shfl_xor_sync(0xffffffffu, q, o);
    if ((tid & 31) == 0) red[tid >> 5] = q;
    __syncthreads();
    float qt = red[0];
#pragma unroll
    for (int i = 1; i < 8; i++) qt += red[i];

    float stdv = sqrtf(qt * (1.f / (DM - 1)));
    float inv = 1.f / (stdv + 1e-6f);
#pragma unroll
    for (int j = 0; j < 4; j++) {
        int i = tid + j * 256;
        out[(size_t)row * DM + i] = alpha[i] * (loc[j] - mean) * inv + beta[i];
    }
}

// ---------------------------------------------------------------------------
// Launch sequence
// ---------------------------------------------------------------------------
extern "C" void kernel_launch(void* const* d_in, const int* in_sizes, int n_in,
                              void* d_out, int out_size)
{
    const float* x      = (const float*)d_in[0];
    const float* W_in   = (const float*)d_in[1];
    const float* b_in   = (const float*)d_in[2];
    const float* conv_w = (const float*)d_in[3];
    const float* conv_b = (const float*)d_in[4];
    const float* W_xp   = (const float*)d_in[5];
    const float* b_xp   = (const float*)d_in[6];
    const float* W_dt   = (const float*)d_in[7];
    const float* b_dt   = (const float*)d_in[8];
    const float* A_log  = (const float*)d_in[9];
    const float* D_skip = (const float*)d_in[10];
    const float* W_out  = (const float*)d_in[11];
    const float* b_out  = (const float*)d_in[12];
    const float* alpha  = (const float*)d_in[13];
    const float* beta   = (const float*)d_in[14];
    float* out = (float*)d_out;

    float *mmout;
    __half *xzh, *dbch, *xh, *xconvh, *yzh, *wt_in, *wt_dtx, *wt_out;
    cudaGetSymbolAddress((void**)&xzh,    g_xzh);
    cudaGetSymbolAddress((void**)&dbch,   g_dbch);
    cudaGetSymbolAddress((void**)&mmout,  g_mmout);
    cudaGetSymbolAddress((void**)&xh,     g_xh);
    cudaGetSymbolAddress((void**)&xconvh, g_xconvh);
    cudaGetSymbolAddress((void**)&yzh,    g_yzh);
    cudaGetSymbolAddress((void**)&wt_in,  g_wt_in);
    cudaGetSymbolAddress((void**)&wt_dtx, g_wt_dtx);
    cudaGetSymbolAddress((void**)&wt_out, g_wt_out);

    cudaFuncSetAttribute((const void*)gemm_mma<128,128,64,32,256,0,1>,
                         cudaFuncAttributeMaxDynamicSharedMemorySize, GSMEM_128);
    cudaFuncSetAttribute((const void*)gemm_mma<128,128,64,32,256,2,1>,
                         cudaFuncAttributeMaxDynamicSharedMemorySize, GSMEM_128);
    cudaFuncSetAttribute((const void*)gemm_mma<64,128,64,32,128,3,0>,
                         cudaFuncAttributeMaxDynamicSharedMemorySize, GSMEM_G3);

    // 0) fused prep: to_half + all weight transposes
    prep_all<<<12352, 256>>>(x, W_in, W_dt, W_xp, W_out);                       // 0

    // 1) in-proj, half output
    gemm_mma<128,128,64,32,256,0,1><<<dim3((2 * DI) / 128, MROWS / 128), 256, GSMEM_128>>>(
        xh, wt_in, b_in, nullptr, xzh, MROWS, 2 * DI, DM);                      // 1

    // 2) conv + silu (half2)
    conv_silu<<<(MROWS * DI / 2) / 256, 256>>>(conv_w, conv_b);                 // 2

    // 3) combined delta/B/C GEMM, half output (profiler slot)
    gemm_mma<128,128,64,32,256,2,1><<<dim3(NDBC / 128, MROWS / 128), 256, GSMEM_128>>>(
        xconvh, wt_dtx, b_dt, b_xp, dbch, MROWS, NDBC, DI);                     // 3

    // 4) chunked selective scan
    scan_pass1<<<(B_SZ * DI / 128) * NCHUNK, 128>>>(A_log);                     // 4
    scan_combine<<<(B_SZ * DI * DS) / 256, 256>>>(A_log);                       // 5
    scan_pass2<<<(B_SZ * DI / 128) * NCHUNK, 128>>>(A_log, D_skip);             // 6

    // 5) out-proj with fused residual add (fp32 output)
    gemm_mma<64,128,64,32,128,3,0><<<dim3(DM / 128, MROWS / 64), 128, GSMEM_G3>>>(
        yzh, wt_out, b_out, x, mmout, MROWS, DM, DI);                           // 7

    // 6) layernorm
    layernorm<<<MROWS, 256>>>(alpha, beta, out);                                // 8
}

// round 16
// speedup vs baseline: 1.5393x; 1.5393x over previous
#include <cuda_runtime.h>
#include <cuda_fp16.h>
#include <math.h>
#include <stdint.h>

#define B_SZ   2
#define LSEQ   1024
#define DM     1024
#define DI     2048
#define DS     16
#define MROWS  (B_SZ * LSEQ)   // 2048
#define NCHUNK 16
#define CLEN   (LSEQ / NCHUNK) // 64
#define NDBC   2176            // 2048 delta + 32 B/C + 96 pad (17 * 128)

// ---------------------------------------------------------------------------
// Scratch (__device__ globals; zero-initialized -> padding rows stay 0)
// ---------------------------------------------------------------------------
__device__ __half g_xzh[MROWS * 2 * DI];
__device__ __half g_xconvh[MROWS * DI];
__device__ __half g_dbch[MROWS * NDBC];
__device__ float  g_mmout[MROWS * DM];
__device__ __half g_xh[MROWS * DM];
__device__ __half g_yzh[MROWS * DI];
__device__ __half g_wt_in[(2 * DI) * DM];
__device__ __half g_wt_dtx[NDBC * DI];
__device__ __half g_wt_out[DM * DI];
__device__ float  g_E[B_SZ * DI * NCHUNK * DS];
__device__ float  g_S[B_SZ * DI * NCHUNK];
__device__ float  g_Hi[B_SZ * DI * NCHUNK * DS];

// ---------------------------------------------------------------------------
// helpers
// ---------------------------------------------------------------------------
static __device__ __forceinline__ uint32_t smem_u32(const void* p) {
    uint32_t a;
    asm("{ .reg .u64 t; cvta.to.shared.u64 t, %1; cvt.u32.u64 %0, t; }"
        : "=r"(a) : "l"(p));
    return a;
}
static __device__ __forceinline__ void cp_async16(uint32_t sa, const void* ga) {
    asm volatile("cp.async.cg.shared.global [%0], [%1], 16;" :: "r"(sa), "l"(ga));
}
static __device__ __forceinline__ void cp_commit() {
    asm volatile("cp.async.commit_group;" ::: "memory");
}
static __device__ __forceinline__ void cp_wait2() {
    asm volatile("cp.async.wait_group 2;" ::: "memory");
}
static __device__ __forceinline__ float ex2f(float x) {
    float r;
    asm("ex2.approx.f32 %0, %1;" : "=f"(r) : "f"(x));
    return r;
}
static __device__ __forceinline__ void mma16816(float* d, const uint32_t* a,
                                                const uint32_t* b) {
    asm volatile(
        "mma.sync.aligned.m16n8k16.row.col.f32.f16.f16.f32 "
        "{%0,%1,%2,%3}, {%4,%5,%6,%7}, {%8,%9}, {%0,%1,%2,%3};"
        : "+f"(d[0]), "+f"(d[1]), "+f"(d[2]), "+f"(d[3])
        : "r"(a[0]), "r"(a[1]), "r"(a[2]), "r"(a[3]), "r"(b[0]), "r"(b[1]));
}
static __device__ __forceinline__ void ldsm_x4(uint32_t* r, uint32_t addr) {
    asm volatile("ldmatrix.sync.aligned.m8n8.x4.shared.b16 {%0,%1,%2,%3}, [%4];"
                 : "=r"(r[0]), "=r"(r[1]), "=r"(r[2]), "=r"(r[3]) : "r"(addr));
}
static __device__ __forceinline__ void ldsm_x2(uint32_t* r, uint32_t addr) {
    asm volatile("ldmatrix.sync.aligned.m8n8.x2.shared.b16 {%0,%1}, [%2];"
                 : "=r"(r[0]), "=r"(r[1]) : "r"(addr));
}

// ---------------------------------------------------------------------------
// fp16 mma.sync GEMM (fp32 accum), templated tiles — EXACT R14 template.
// __launch_bounds__(NTHR, 2) is load-bearing: caps regs at 128 -> occ 2.
// EPI: 0 bias; 1 bias+softplus; 2 combined delta/BC epilogue.
// OUTH: 1 -> store __half, 0 -> store float.
// ---------------------------------------------------------------------------
#define BK 32
#define STRDH 40
#define NSTG 4

template <int TBM, int TBN, int TWM, int TWN, int NTHR, int EPI, int OUTH>
__global__ __launch_bounds__(NTHR, 2)
void gemm_mma(const __half* __restrict__ A, const __half* __restrict__ Bt,
              const float* __restrict__ bias, const float* __restrict__ bias2,
              void* __restrict__ Cv, int M, int N, int K)
{
    constexpr int ATILE = TBM * STRDH;
    constexpr int BTILE = TBN * STRDH;
    constexpr int NWN = TBN / TWN;
    constexpr int MI = TWM / 16;
    constexpr int NI = TWN / 8;

    extern __shared__ __half smh[];
    __half* As = smh;
    __half* Bs = smh + NSTG * ATILE;

    const int tid  = threadIdx.x;
    const int lane = tid & 31;
    const int wid  = tid >> 5;
    const int wm   = (wid / NWN) * TWM;
    const int wn   = (wid % NWN) * TWN;
    const int bm = blockIdx.y * TBM;
    const int bn = blockIdx.x * TBN;

    float acc[MI][NI][4];
#pragma unroll
    for (int mi = 0; mi < MI; mi++)
#pragma unroll
        for (int ni = 0; ni < NI; ni++)
#pragma unroll
            for (int r = 0; r < 4; r++) acc[mi][ni][r] = 0.f;

    auto load_tile = [&](int j) {
        const int stg = j % NSTG;
        const int k0 = j * BK;
        __half* ad = As + stg * ATILE;
        __half* bd = Bs + stg * BTILE;
#pragma unroll
        for (int ch = tid; ch < TBM * 4; ch += NTHR) {
            int row = ch >> 2, col = ch & 3;
            cp_async16(smem_u32(ad + row * STRDH + col * 8),
                       A + (size_t)(bm + row) * K + k0 + col * 8);
        }
#pragma unroll
        for (int ch = tid; ch < TBN * 4; ch += NTHR) {
            int row = ch >> 2, col = ch & 3;
            cp_async16(smem_u32(bd + row * STRDH + col * 8),
                       Bt + (size_t)(bn + row) * K + k0 + col * 8);
        }
    };

    const int KT = K / BK;
    load_tile(0); cp_commit();
    load_tile(1); cp_commit();
    load_tile(2); cp_commit();

    for (int i = 0; i < KT; i++) {
        cp_wait2();
        __syncthreads();
        if (i + 3 < KT) load_tile(i + 3);
        cp_commit();

        const int stg = i % NSTG;
        const __half* ad = As + stg * ATILE;
        const __half* bd = Bs + stg * BTILE;

#pragma unroll
        for (int kk = 0; kk < BK; kk += 16) {
            uint32_t af[MI][4];
            uint32_t bf[NI][2];
#pragma unroll
            for (int mi = 0; mi < MI; mi++) {
                uint32_t a_addr = smem_u32(
                    ad + (wm + mi * 16 + (lane & 15)) * STRDH + kk + (lane >> 4) * 8);
                ldsm_x4(af[mi], a_addr);
            }
#pragma unroll
            for (int ni = 0; ni < NI; ni++) {
                uint32_t b_addr = smem_u32(
                    bd + (wn + ni * 8 + (lane & 7)) * STRDH + kk + ((lane >> 3) & 1) * 8);
                ldsm_x2(bf[ni], b_addr);
            }
#pragma unroll
            for (int mi = 0; mi < MI; mi++)
#pragma unroll
                for (int ni = 0; ni < NI; ni++)
                    mma16816(acc[mi][ni], af[mi], bf[ni]);
        }
    }

    // ---- epilogue ---------------------------------------------------------
#pragma unroll
    for (int mi = 0; mi < MI; mi++) {
#pragma unroll
        for (int ni = 0; ni < NI; ni++) {
            int r0 = bm + wm + mi * 16 + (lane >> 2);
            int c0 = bn + wn + ni * 8 + (lane & 3) * 2;
            float2 bv;
            bool sp;
            if (EPI == 2) {
                if (c0 < DI)            { bv = *(const float2*)(bias + c0);       sp = true;  }
                else if (c0 < DI + 32)  { bv = *(const float2*)(bias2 + c0 - DI); sp = false; }
                else                    { bv = make_float2(0.f, 0.f);             sp = false; }
            } else {
                bv = *(const float2*)(bias + c0);
                sp = (EPI == 1);
            }
            float2 v0, v1;
            v0.x = acc[mi][ni][0] + bv.x;
            v0.y = acc[mi][ni][1] + bv.y;
            v1.x = acc[mi][ni][2] + bv.x;
            v1.y = acc[mi][ni][3] + bv.y;
            if (sp) {
                v0.x = (v0.x > 15.f) ? v0.x : log1pf(__expf(v0.x));
                v0.y = (v0.y > 15.f) ? v0.y : log1pf(__expf(v0.y));
                v1.x = (v1.x > 15.f) ? v1.x : log1pf(__expf(v1.x));
                v1.y = (v1.y > 15.f) ? v1.y : log1pf(__expf(v1.y));
            }
            if (OUTH) {
                __half* C = (__half*)Cv;
                *(__half2*)(C + (size_t)r0 * N + c0) = __floats2half2_rn(v0.x, v0.y);
                *(__half2*)(C + (size_t)(r0 + 8) * N + c0) = __floats2half2_rn(v1.x, v1.y);
            } else {
                float* C = (float*)Cv;
                *(float2*)(C + (size_t)r0 * N + c0) = v0;
                *(float2*)(C + (size_t)(r0 + 8) * N + c0) = v1;
            }
        }
    }
}

#define GSMEM_128 ((128 + 128) * STRDH * 2 * NSTG)   // 81920
#define GSMEM_G3  ((64 + 128) * STRDH * 2 * NSTG)    // 61440

// ---------------------------------------------------------------------------
// Fused prep: to_half(x) + 4 weight transposes, one launch.
// Block ranges: [0,2048) to_half | [2048,6144) W_in | [6144,10240) W_dt |
//               [10240,10304) W_xp | [10304,12352) W_out
// ---------------------------------------------------------------------------
static __device__ __forceinline__ void tw_tile(const float* __restrict__ W,
                                               __half* __restrict__ Wt,
                                               int K, int N, int bx, int by,
                                               float (*t)[33])
{
    int n0 = bx * 32, k0 = by * 32;
    int tx = threadIdx.x & 31, ty = threadIdx.x >> 5;
#pragma unroll
    for (int i = ty; i < 32; i += 8)
        t[i][tx] = W[(size_t)(k0 + i) * N + n0 + tx];
    __syncthreads();
#pragma unroll
    for (int i = ty; i < 32; i += 8)
        Wt[(size_t)(n0 + i) * K + k0 + tx] = __float2half(t[tx][i]);
}

__global__ __launch_bounds__(256)
void prep_all(const float* __restrict__ x, const float* __restrict__ W_in,
              const float* __restrict__ W_dt, const float* __restrict__ W_xp,
              const float* __restrict__ W_out)
{
    __shared__ float t[32][33];
    int b = blockIdx.x;
    if (b < 2048) {                       // to_half, float4 per thread
        int i = (b * 256 + threadIdx.x) * 4;
        float4 v = *(const float4*)(x + i);
        *(__half2*)(g_xh + i) = __floats2half2_rn(v.x, v.y);
        *(__half2*)(g_xh + i + 2) = __floats2half2_rn(v.z, v.w);
        return;
    }
    b -= 2048;
    if (b < 4096) { tw_tile(W_in, g_wt_in, DM, 2 * DI, b & 127, b >> 7, t); return; }
    b -= 4096;
    if (b < 4096) { tw_tile(W_dt, g_wt_dtx, DI, DI, b & 63, b >> 6, t); return; }
    b -= 4096;
    if (b < 64)  { tw_tile(W_xp, g_wt_dtx + (size_t)DI * DI, DI, 32, 0, b, t); return; }
    b -= 64;
    tw_tile(W_out, g_wt_out, DI, DM, b & 31, b >> 5, t);
}

// ---------------------------------------------------------------------------
// Depthwise causal conv (width 4) + SiLU — EXACT R14 version (scalar)
// ---------------------------------------------------------------------------
__global__ void conv_silu(const float* __restrict__ cw, const float* __restrict__ cb)
{
    int idx = blockIdx.x * 256 + threadIdx.x;
    if (idx >= MROWS * DI) return;
    int d  = idx & (DI - 1);
    int lm = idx >> 11;
    int l  = lm & (LSEQ - 1);

    const __half* xp = g_xzh + (size_t)lm * (2 * DI) + d;
    float acc = cb[d];
#pragma unroll
    for (int j = 0; j < 4; j++) {
        int ll = l - 3 + j;
        if (ll >= 0) acc += __half2float(xp[(j - 3) * (2 * DI)]) * cw[d * 4 + j];
    }
    float v = acc / (1.f + __expf(-acc));
    g_xconvh[idx] = __float2half(v);
}

// ---------------------------------------------------------------------------
// Chunked scan, d-parallel — EXACT R14 versions
// ---------------------------------------------------------------------------
#define LOG2E 1.44269504088896f

__global__ __launch_bounds__(128)
void scan_pass1(const float* __restrict__ A_log)
{
    int chunk = blockIdx.x & (NCHUNK - 1);
    int bdg   = blockIdx.x >> 4;
    int bd    = bdg * 128 + threadIdx.x;
    int b     = bd >> 11;
    int d     = bd & (DI - 1);

    __shared__ float bcs[CLEN][DS];
    const __half* bcp = g_dbch + ((size_t)b * LSEQ + chunk * CLEN) * NDBC + DI;
    for (int i = threadIdx.x; i < CLEN * DS; i += 128) {
        int t = i >> 4, s = i & 15;
        bcs[t][s] = __half2float(bcp[(size_t)t * NDBC + s]);
    }
    __syncthreads();

    float Av[DS];
#pragma unroll
    for (int s = 0; s < DS; s++)
        Av[s] = -__expf(A_log[d * DS + s]) * LOG2E;

    float h[DS];
#pragma unroll
    for (int s = 0; s < DS; s++) h[s] = 0.f;
    float S = 0.f;

    const __half* dp = g_dbch + ((size_t)b * LSEQ + chunk * CLEN) * NDBC + d;
    const __half* xp = g_xconvh + ((size_t)b * LSEQ + chunk * CLEN) * DI + d;

    for (int t = 0; t < CLEN; t++) {
        float dv = __half2float(dp[(size_t)t * NDBC]);
        float xv = __half2float(xp[(size_t)t * DI]);
        float u = dv * xv;
        S += dv;
#pragma unroll
        for (int s = 0; s < DS; s++)
            h[s] = fmaf(ex2f(dv * Av[s]), h[s], u * bcs[t][s]);
    }

    int gid = bd * NCHUNK + chunk;
#pragma unroll
    for (int s = 0; s < DS; s++) g_E[gid * DS + s] = h[s];
    g_S[gid] = S;
}

__global__ __launch_bounds__(256)
void scan_combine(const float* __restrict__ A_log)
{
    int idx = blockIdx.x * 256 + threadIdx.x;
    int s  = idx & 15;
    int bd = idx >> 4;
    int d  = bd & (DI - 1);
    float Av = -__expf(A_log[d * DS + s]);
    float H = 0.f;
#pragma unroll
    for (int c = 0; c < NCHUNK; c++) {
        int gid = bd * NCHUNK + c;
        g_Hi[gid * DS + s] = H;
        H = fmaf(__expf(Av * g_S[gid]), H, g_E[gid * DS + s]);
    }
}

__global__ __launch_bounds__(128)
void scan_pass2(const float* __restrict__ A_log, const float* __restrict__ D_skip)
{
    int chunk = blockIdx.x & (NCHUNK - 1);
    int bdg   = blockIdx.x >> 4;
    int bd    = bdg * 128 + threadIdx.x;
    int b     = bd >> 11;
    int d     = bd & (DI - 1);

    __shared__ float bcs[CLEN][2 * DS];
    const __half* bcp = g_dbch + ((size_t)b * LSEQ + chunk * CLEN) * NDBC + DI;
    for (int i = threadIdx.x; i < CLEN * 2 * DS; i += 128) {
        int t = i >> 5, j = i & 31;
        bcs[t][j] = __half2float(bcp[(size_t)t * NDBC + j]);
    }
    __syncthreads();

    float Av[DS];
#pragma unroll
    for (int s = 0; s < DS; s++)
        Av[s] = -__expf(A_log[d * DS + s]) * LOG2E;
    float Dv = D_skip[d];

    int gid = bd * NCHUNK + chunk;
    float h[DS];
#pragma unroll
    for (int s = 0; s < DS; s++) h[s] = g_Hi[gid * DS + s];

    const __half* dp = g_dbch + ((size_t)b * LSEQ + chunk * CLEN) * NDBC + d;
    const __half* xp = g_xconvh + ((size_t)b * LSEQ + chunk * CLEN) * DI + d;
    const __half* zp = g_xzh + ((size_t)b * LSEQ + chunk * CLEN) * (2 * DI) + DI + d;
    __half* yp = g_yzh + ((size_t)b * LSEQ + chunk * CLEN) * DI + d;

    for (int t = 0; t < CLEN; t++) {
        float dv = __half2float(dp[(size_t)t * NDBC]);
        float xv = __half2float(xp[(size_t)t * DI]);
        float z  = __half2float(zp[(size_t)t * (2 * DI)]);
        float u = dv * xv;
        float y = Dv * xv;
#pragma unroll
        for (int s = 0; s < DS; s++) {
            h[s] = fmaf(ex2f(dv * Av[s]), h[s], u * bcs[t][s]);
            y = fmaf(h[s], bcs[t][DS + s], y);
        }
        yp[(size_t)t * DI] = __float2half(y * (z / (1.f + __expf(-z))));
    }
}

// ---------------------------------------------------------------------------
// residual add + LayerNorm — EXACT R14 version
// ---------------------------------------------------------------------------
__global__ __launch_bounds__(256)
void add_layernorm(const float* __restrict__ res, const float* __restrict__ alpha,
                   const float* __restrict__ beta, float* __restrict__ out)
{
    __shared__ float red[8];
    int row = blockIdx.x;
    int tid = threadIdx.x;

    float loc[4];
    float sgm = 0.f;
#pragma unroll
    for (int j = 0; j < 4; j++) {
        int i = tid + j * 256;
        loc[j] = res[(size_t)row * DM + i] + g_mmout[(size_t)row * DM + i];
        sgm += loc[j];
    }
#pragma unroll
    for (int o = 16; o; o >>= 1) sgm += __shfl_xor_sync(0xffffffffu, sgm, o);
    if ((tid & 31) == 0) red[tid >> 5] = sgm;
    __syncthreads();
    float tot = red[0];
#pragma unroll
    for (int i = 1; i < 8; i++) tot += red[i];
    float mean = tot * (1.f / DM);
    __syncthreads();

    float q = 0.f;
#pragma unroll
    for (int j = 0; j < 4; j++) {
        float df = loc[j] - mean;
        q += df * df;
    }
#pragma unroll
    for (int o = 16; o; o >>= 1) q += __shfl_xor_sync(0xffffffffu, q, o);
    if ((tid & 31) == 0) red[tid >> 5] = q;
    __syncthreads();
    float qt = red[0];
#pragma unroll
    for (int i = 1; i < 8; i++) qt += red[i];

    float stdv = sqrtf(qt * (1.f / (DM - 1)));
    float inv = 1.f / (stdv + 1e-6f);
#pragma unroll
    for (int j = 0; j < 4; j++) {
        int i = tid + j * 256;
        out[(size_t)row * DM + i] = alpha[i] * (loc[j] - mean) * inv + beta[i];
    }
}

// ---------------------------------------------------------------------------
// Launch sequence (gemm2 now at launch index 3 = profiler slot)
// ---------------------------------------------------------------------------
extern "C" void kernel_launch(void* const* d_in, const int* in_sizes, int n_in,
                              void* d_out, int out_size)
{
    const float* x      = (const float*)d_in[0];
    const float* W_in   = (const float*)d_in[1];
    const float* b_in   = (const float*)d_in[2];
    const float* conv_w = (const float*)d_in[3];
    const float* conv_b = (const float*)d_in[4];
    const float* W_xp   = (const float*)d_in[5];
    const float* b_xp   = (const float*)d_in[6];
    const float* W_dt   = (const float*)d_in[7];
    const float* b_dt   = (const float*)d_in[8];
    const float* A_log  = (const float*)d_in[9];
    const float* D_skip = (const float*)d_in[10];
    const float* W_out  = (const float*)d_in[11];
    const float* b_out  = (const float*)d_in[12];
    const float* alpha  = (const float*)d_in[13];
    const float* beta   = (const float*)d_in[14];
    float* out = (float*)d_out;

    float *mmout;
    __half *xzh, *dbch, *xh, *xconvh, *yzh, *wt_in, *wt_dtx, *wt_out;
    cudaGetSymbolAddress((void**)&xzh,    g_xzh);
    cudaGetSymbolAddress((void**)&dbch,   g_dbch);
    cudaGetSymbolAddress((void**)&mmout,  g_mmout);
    cudaGetSymbolAddress((void**)&xh,     g_xh);
    cudaGetSymbolAddress((void**)&xconvh, g_xconvh);
    cudaGetSymbolAddress((void**)&yzh,    g_yzh);
    cudaGetSymbolAddress((void**)&wt_in,  g_wt_in);
    cudaGetSymbolAddress((void**)&wt_dtx, g_wt_dtx);
    cudaGetSymbolAddress((void**)&wt_out, g_wt_out);

    cudaFuncSetAttribute((const void*)gemm_mma<128,128,64,32,256,0,1>,
                         cudaFuncAttributeMaxDynamicSharedMemorySize, GSMEM_128);
    cudaFuncSetAttribute((const void*)gemm_mma<128,128,64,32,256,2,1>,
                         cudaFuncAttributeMaxDynamicSharedMemorySize, GSMEM_128);
    cudaFuncSetAttribute((const void*)gemm_mma<64,128,64,32,128,0,0>,
                         cudaFuncAttributeMaxDynamicSharedMemorySize, GSMEM_G3);

    // 0) fused prep: to_half + all weight transposes
    prep_all<<<12352, 256>>>(x, W_in, W_dt, W_xp, W_out);                       // 0

    // 1) in-proj, half output
    gemm_mma<128,128,64,32,256,0,1><<<dim3((2 * DI) / 128, MROWS / 128), 256, GSMEM_128>>>(
        xh, wt_in, b_in, nullptr, xzh, MROWS, 2 * DI, DM);                      // 1

    // 2) conv + silu (R14 scalar)
    conv_silu<<<(MROWS * DI) / 256, 256>>>(conv_w, conv_b);                     // 2

    // 3) combined delta/B/C GEMM, half output (PROFILER SLOT)
    gemm_mma<128,128,64,32,256,2,1><<<dim3(NDBC / 128, MROWS / 128), 256, GSMEM_128>>>(
        xconvh, wt_dtx, b_dt, b_xp, dbch, MROWS, NDBC, DI);                     // 3

    // 4) chunked selective scan
    scan_pass1<<<(B_SZ * DI / 128) * NCHUNK, 128>>>(A_log);                     // 4
    scan_combine<<<(B_SZ * DI * DS) / 256, 256>>>(A_log);                       // 5
    scan_pass2<<<(B_SZ * DI / 128) * NCHUNK, 128>>>(A_log, D_skip);             // 6

    // 5) out-proj (fp32 output, EPI=0 — R14 config)
    gemm_mma<64,128,64,32,128,0,0><<<dim3(DM / 128, MROWS / 64), 128, GSMEM_G3>>>(
        yzh, wt_out, b_out, nullptr, mmout, MROWS, DM, DI);                     // 7

    // 6) residual + layernorm (R14 version)
    add_layernorm<<<MROWS, 256>>>(x, alpha, beta, out);                         // 8
}